// round 5
// baseline (speedup 1.0000x reference)
#include <cuda_runtime.h>
#include <math.h>
#include <limits.h>
#include <stdint.h>

// Problem constants
#define TT 10000
#define BB 4096
#define NTH 1024
#define EPT 10            // elements per thread in scan kernel (NTH*EPT >= TT)
#define CH 8              // t-steps per chunk in kill kernel
#define KGX 4             // kill grid x  (KGX*256*4 == BB lanes)
#define KGY 140           // kill grid y
#define NBLK (KGX * KGY)  // total kill blocks (all reach the ticket counter)

#define LOG_GAMMA_C ( 0.019802627296179713f)   // ln(1.02)
#define ALPHA_C     (-1.0050335853501451e-05f) // ln(0.99)/1000
#define INIT_LOGW_C (-1.3943265327605025f)     // ln(0.248)
#define INIT_LOGP_C (-6.907755278982137f)      // ln(0.001)
#define INV_TEMP_C  (0.001f)
#define EPSF        (1e-12f)

// Scratch (no allocations allowed)
__device__ float2       g_row[TT];      // per-t {thr, rm}: u2 filter threshold, r - eps
__device__ float        g_pref[TT + 1]; // exclusive prefix of W_t = exp(logw_{t+1}/TEMP)
__device__ int          g_tactive;      // first t beyond which kill is impossible
__device__ int          g_tkill[BB];    // per-lane first kill step (TT = never)
__device__ unsigned int g_done;         // kill-block completion ticket

// ---------------------------------------------------------------------------
// cp.async helpers (LDGSTS): fire-and-forget 16B gmem->smem copies.
// ---------------------------------------------------------------------------
__device__ __forceinline__ void cp_async16(uint32_t saddr, const void* gaddr) {
    asm volatile("cp.async.cg.shared.global [%0], [%1], 16;\n"
                 :: "r"(saddr), "l"(gaddr) : "memory");
}
__device__ __forceinline__ void cp_async_wait_all() {
    asm volatile("cp.async.commit_group;\ncp.async.wait_group 0;\n" ::: "memory");
}

// ---------------------------------------------------------------------------
// Block-wide exclusive scan via warp shuffles (2 barriers)
// ---------------------------------------------------------------------------
__device__ __forceinline__ float block_exscan(float v) {
    __shared__ float ws[32];
    const int lane = threadIdx.x & 31;
    const int wid  = threadIdx.x >> 5;
    float s = v;
#pragma unroll
    for (int o = 1; o < 32; o <<= 1) {
        float n = __shfl_up_sync(0xffffffffu, s, o);
        if (lane >= o) s += n;
    }
    float exw = __shfl_up_sync(0xffffffffu, s, 1);
    if (lane == 0) exw = 0.0f;
    if (lane == 31) ws[wid] = s;
    __syncthreads();
    if (wid == 0) {
        float t = ws[lane];
#pragma unroll
        for (int o = 1; o < 32; o <<= 1) {
            float n = __shfl_up_sync(0xffffffffu, t, o);
            if (lane >= o) t += n;
        }
        float exb = __shfl_up_sync(0xffffffffu, t, 1);
        if (lane == 0) exb = 0.0f;
        ws[lane] = exb;
    }
    __syncthreads();
    return ws[wid] + exw;
}

// ---------------------------------------------------------------------------
// K1 (single block): everything that depends only on acts.
// Key accuracy fact: logp only DECREASES from ln(0.001), so e = exp(logp) <= 1e-3.
// That makes log1p(-e), e/(1-e) and exp(-28r) all tiny-argument -> low-order
// polynomials (abs errors <= 3e-8), leaving 1 MUFU exp per element in part 3.
// ---------------------------------------------------------------------------
__global__ void __launch_bounds__(NTH) scan_kernel(const float* __restrict__ acts) {
    const int tid  = threadIdx.x;
    const int base = tid * EPT;
    const bool act = (base < TT);

    float f[EPT], c[EPT], d[EPT], w[EPT];
    float csum = 0.0f;
    if (act) {
#pragma unroll
        for (int i = 0; i < EPT; ++i) {
            float a = acts[base + i];
            f[i] = __expf(a);
            c[i] = LOG_GAMMA_C + __logf(1.0f - f[i]);
            csum += c[i];
        }
    }
    float coff = block_exscan(act ? csum : 0.0f);

    float dsum = 0.0f, wsum = 0.0f;
    if (act) {
        float lw0 = INIT_LOGW_C + coff;        // logw at first local element
        float elw = __expf(lw0);                // exp(logw_t) anchor, multiplicative recur
        float wv  = __expf(lw0 * INV_TEMP_C);   // exp(logw_t/TEMP) anchor
        float lwl = 0.0f;                       // local c prefix
#pragma unroll
        for (int i = 0; i < EPT; ++i) {
            d[i] = ALPHA_C * f[i] * elw;        // uses OLD logw (matches ref)
            elw *= 1.02f * (1.0f - f[i]);       // exp(logw_{t+1})
            lwl += c[i];
            float x = lwl * INV_TEMP_C;         // |x| <= 2e-4: 2nd-order exp
            w[i] = wv * (1.0f + x * (1.0f + 0.5f * x));
            dsum += d[i];
            wsum += w[i];
        }
    }
    float doff = block_exscan(act ? dsum : 0.0f);
    float woff = block_exscan(act ? wsum : 0.0f);

    int poss = -1;
    if (act) {
        float lp = INIT_LOGP_C + doff;
        float pw = woff;
#pragma unroll
        for (int i = 0; i < EPT; ++i) {
            g_pref[base + i] = pw;  pw += w[i];
            float e = __expf(lp);                       // e <= 1e-3 always
            float logit = lp + e * (1.0f + 0.5f * e);   // lp - log1p(-e), err ~ e^3/3
            float r = e * (1.0f + e);                   // e/(1-e), err ~ e^3
            // Necessary condition for kill: u2 + eps > exp(-27.631*r)
            // (|log(u1+eps)| <= 27.631). 28.0 / -1e-5 = safety margin.
            float x = 28.0f * r;                        // x <= 0.029
            float thr = 1.0f - x * (1.0f - 0.5f * x * (1.0f - 0.33333334f * x)) - 1e-5f;
            g_row[base + i] = make_float2(thr, r - EPSF);
            // noise <= 19.95 always, so logit < -20.5 => kill impossible
            if (logit > -20.5f) poss = base + i;
            lp += d[i];
        }
        if (base + EPT == TT) g_pref[TT] = pw;
    }

    __shared__ int sh_ta;
    if (tid == 0) sh_ta = 0;
    __syncthreads();
    if (poss >= 0) atomicMax(&sh_ta, poss + 1);
    __syncthreads();
    if (tid == 0) { g_tactive = sh_ta; g_done = 0u; }

    // reset per-lane kill step every launch (graph replays)
    for (int b = tid; b < BB; b += NTH) g_tkill[b] = TT;
}

// ---------------------------------------------------------------------------
// K2: find first kill per lane + fused final reduction (last-block pattern).
// u2 rows are staged through shared memory with cp.async so all CH row loads
// are guaranteed in flight together (no register-pressure serialization).
// Exact kill condition (real-math equivalent of the reference):
//   sigmoid(logit + noise) > 0.5
//   <=> L2/L1 + eps < exp(logit) = r        (L1 = log(u1+eps) < 0, L2 = log(u2+eps))
//   <=> L2 > (r - eps) * L1                 (multiply by L1 < 0 flips)
// ---------------------------------------------------------------------------
__global__ void __launch_bounds__(256) kill_kernel(const float* __restrict__ u1,
                                                   const float* __restrict__ u2,
                                                   float* __restrict__ out) {
    __shared__ float4 s_u2[CH][256];   // 32 KB staging

    const int ta      = g_tactive;
    const int nchunks = (ta + CH - 1) / CH;
    const int tid     = threadIdx.x;

    const int q = blockIdx.x * 256 + tid;          // quad index (0..1023)
    const int b = q << 2;
    const float4* __restrict__ u2v = (const float4*)u2;
    const uint32_t s_base = (uint32_t)__cvta_generic_to_shared(&s_u2[0][tid]);

    int k0 = INT_MAX, k1 = INT_MAX, k2 = INT_MAX, k3 = INT_MAX;

    for (int cy = blockIdx.y; cy < nchunks; cy += KGY) {
        const int t0 = cy * CH;

        // stage CH rows; back-to-back LDGSTS => MLP = CH guaranteed
#pragma unroll
        for (int i = 0; i < CH; ++i) {
            int tt = min(t0 + i, TT - 1);
            cp_async16(s_base + i * (256 * 16), u2v + tt * (BB / 4) + q);
        }
        cp_async_wait_all();   // each thread reads only its own slots: no barrier

#pragma unroll
        for (int i = 0; i < CH; ++i) {
            const int tt = t0 + i;
            if (tt >= ta) break;
            const float2 row = g_row[tt];          // uniform -> broadcast
            const float4 vv  = s_u2[i][tid];
            const float  m   = fmaxf(fmaxf(vv.x, vv.y), fmaxf(vv.z, vv.w));
            if (m > row.x) {
                const int   rb = tt * BB + b;      // fits in 32 bits
                const float rm = row.y;
                if (vv.x > row.x) {
                    float L1 = __logf(u1[rb + 0] + EPSF), L2 = __logf(vv.x + EPSF);
                    if (L2 > rm * L1) k0 = min(k0, tt);
                }
                if (vv.y > row.x) {
                    float L1 = __logf(u1[rb + 1] + EPSF), L2 = __logf(vv.y + EPSF);
                    if (L2 > rm * L1) k1 = min(k1, tt);
                }
                if (vv.z > row.x) {
                    float L1 = __logf(u1[rb + 2] + EPSF), L2 = __logf(vv.z + EPSF);
                    if (L2 > rm * L1) k2 = min(k2, tt);
                }
                if (vv.w > row.x) {
                    float L1 = __logf(u1[rb + 3] + EPSF), L2 = __logf(vv.w + EPSF);
                    if (L2 > rm * L1) k3 = min(k3, tt);
                }
            }
        }
    }

    if (k0 != INT_MAX) atomicMin(&g_tkill[b + 0], k0);
    if (k1 != INT_MAX) atomicMin(&g_tkill[b + 1], k1);
    if (k2 != INT_MAX) atomicMin(&g_tkill[b + 2], k2);
    if (k3 != INT_MAX) atomicMin(&g_tkill[b + 3], k3);

    // ---- fused reduction: last block to finish gathers Pref[t_kill] & means ----
    __shared__ bool is_last;
    __threadfence();
    if (tid == 0) {
        unsigned int t = atomicAdd(&g_done, 1u);
        is_last = (t == NBLK - 1u);
    }
    __syncthreads();
    if (!is_last) return;
    __threadfence();

    __shared__ double sh[256];
    double s = 0.0;
    for (int bb = tid; bb < BB; bb += 256) s += (double)g_pref[g_tkill[bb]];
    sh[tid] = s;
    __syncthreads();
#pragma unroll
    for (int off = 128; off > 0; off >>= 1) {
        if (tid < off) sh[tid] += sh[tid + off];
        __syncthreads();
    }
    if (tid == 0) out[0] = (float)(sh[0] / (double)BB);
}

// ---------------------------------------------------------------------------
extern "C" void kernel_launch(void* const* d_in, const int* in_sizes, int n_in,
                              void* d_out, int out_size) {
    const float* acts = (const float*)d_in[0];
    const float* u1   = (const float*)d_in[1];
    const float* u2   = (const float*)d_in[2];

    scan_kernel<<<1, NTH>>>(acts);

    dim3 grid(KGX, KGY);
    kill_kernel<<<grid, 256>>>(u1, u2, (float*)d_out);
}

// round 9
// speedup vs baseline: 1.1323x; 1.1323x over previous
#include <cuda_runtime.h>
#include <math.h>
#include <limits.h>
#include <stdint.h>

// Problem constants
#define TT 10000
#define BB 4096
#define NTH 1024
#define EPT 10             // elements per thread in scan kernel (NTH*EPT >= TT)
#define CH 8               // t-steps per chunk in kill kernel
#define KGX 4              // kill grid x  (KGX*256*4 == BB lanes)
#define KGY 138            // kill grid y (covers ta<=1104 in one pass; loop handles more)
#define NBLK (KGX * KGY)   // total kill blocks (all reach the ticket counter)
#define LCAP 2048          // per-block candidate list capacity

#define LOG_GAMMA_C ( 0.019802627296179713f)   // ln(1.02)
#define ALPHA_C     (-1.0050335853501451e-05f) // ln(0.99)/1000
#define INIT_LOGW_C (-1.3943265327605025f)     // ln(0.248)
#define INIT_LOGP_C (-6.907755278982137f)      // ln(0.001)
#define INV_TEMP_C  (0.001f)
#define EPSF        (1e-12f)

// Scratch (no allocations allowed)
__device__ float2       g_row[TT];      // per-t {thr, rm}: u2 filter threshold, r - eps
__device__ float        g_pref[TT + 1]; // exclusive prefix of W_t = exp(logw_{t+1}/TEMP)
__device__ int          g_tactive;      // first t beyond which kill is impossible
__device__ int          g_tkill[BB];    // per-lane first kill step (TT = never)
__device__ unsigned int g_done;         // kill-block completion ticket

// ---------------------------------------------------------------------------
// cp.async helpers
// ---------------------------------------------------------------------------
__device__ __forceinline__ void cp_async16(uint32_t saddr, const void* gaddr) {
    asm volatile("cp.async.cg.shared.global [%0], [%1], 16;\n"
                 :: "r"(saddr), "l"(gaddr) : "memory");
}
__device__ __forceinline__ void cp_async_wait_all() {
    asm volatile("cp.async.commit_group;\ncp.async.wait_group 0;\n" ::: "memory");
}

// ---------------------------------------------------------------------------
// Block-wide exclusive scan via warp shuffles (2 barriers)
// ---------------------------------------------------------------------------
__device__ __forceinline__ float block_exscan(float v) {
    __shared__ float ws[32];
    const int lane = threadIdx.x & 31;
    const int wid  = threadIdx.x >> 5;
    float s = v;
#pragma unroll
    for (int o = 1; o < 32; o <<= 1) {
        float n = __shfl_up_sync(0xffffffffu, s, o);
        if (lane >= o) s += n;
    }
    float exw = __shfl_up_sync(0xffffffffu, s, 1);
    if (lane == 0) exw = 0.0f;
    if (lane == 31) ws[wid] = s;
    __syncthreads();
    if (wid == 0) {
        float t = ws[lane];
#pragma unroll
        for (int o = 1; o < 32; o <<= 1) {
            float n = __shfl_up_sync(0xffffffffu, t, o);
            if (lane >= o) t += n;
        }
        float exb = __shfl_up_sync(0xffffffffu, t, 1);
        if (lane == 0) exb = 0.0f;
        ws[lane] = exb;
    }
    __syncthreads();
    return ws[wid] + exw;
}

// ---------------------------------------------------------------------------
// K1 (single block): everything that depends only on acts.
// e = exp(logp) <= 1e-3 always (logp only decreases), so log1p(-e), e/(1-e)
// and exp(-28r) collapse to tiny-argument polynomials (abs err <= 3e-8).
// ---------------------------------------------------------------------------
__global__ void __launch_bounds__(NTH) scan_kernel(const float* __restrict__ acts) {
    __shared__ float s_acts[TT];   // 40 KB, coalesced staging
    const int tid = threadIdx.x;

    {   // coalesced float4 burst load of acts (TT = 2500 float4s)
        const float4* a4 = (const float4*)acts;
        float4* s4 = (float4*)s_acts;
        for (int i = tid; i < TT / 4; i += NTH) s4[i] = a4[i];
    }
    // reset per-lane kill step + ticket early (independent stores, hide latency)
    for (int b = tid; b < BB; b += NTH) g_tkill[b] = TT;
    if (tid == 0) g_done = 0u;
    __syncthreads();

    const int base = tid * EPT;
    const bool act = (base < TT);

    float f[EPT], c[EPT], d[EPT], w[EPT];
    float csum = 0.0f;
    if (act) {
#pragma unroll
        for (int i = 0; i < EPT; ++i) {
            float a = s_acts[base + i];
            f[i] = __expf(a);
            c[i] = LOG_GAMMA_C + __logf(1.0f - f[i]);
            csum += c[i];
        }
    }
    float coff = block_exscan(act ? csum : 0.0f);

    float dsum = 0.0f, wsum = 0.0f;
    if (act) {
        float lw0 = INIT_LOGW_C + coff;        // logw at first local element
        float elw = __expf(lw0);                // exp(logw_t) anchor, multiplicative recur
        float wv  = __expf(lw0 * INV_TEMP_C);   // exp(logw_t/TEMP) anchor
        float lwl = 0.0f;
#pragma unroll
        for (int i = 0; i < EPT; ++i) {
            d[i] = ALPHA_C * f[i] * elw;        // uses OLD logw (matches ref)
            elw *= 1.02f * (1.0f - f[i]);       // exp(logw_{t+1})
            lwl += c[i];
            float x = lwl * INV_TEMP_C;         // |x| <= 2e-4
            w[i] = wv * (1.0f + x * (1.0f + 0.5f * x));
            dsum += d[i];
            wsum += w[i];
        }
    }
    float doff = block_exscan(act ? dsum : 0.0f);
    float woff = block_exscan(act ? wsum : 0.0f);

    int poss = -1;
    if (act) {
        float lp = INIT_LOGP_C + doff;
        float pw = woff;
#pragma unroll
        for (int i = 0; i < EPT; ++i) {
            g_pref[base + i] = pw;  pw += w[i];
            float e = __expf(lp);                       // e <= 1e-3
            float logit = lp + e * (1.0f + 0.5f * e);   // lp - log1p(-e)
            float r = e * (1.0f + e);                   // e/(1-e)
            // kill needs u2 + eps > exp(-27.631*r); 28.0 / -1e-5 = safety margin
            float x = 28.0f * r;                        // x <= 0.029
            float thr = 1.0f - x * (1.0f - 0.5f * x * (1.0f - 0.33333334f * x)) - 1e-5f;
            g_row[base + i] = make_float2(thr, r - EPSF);
            // noise <= 19.95 always, so logit < -20.5 => kill impossible
            if (logit > -20.5f) poss = base + i;
            lp += d[i];
        }
        if (base + EPT == TT) g_pref[TT] = pw;
    }

    __shared__ int sh_ta;
    if (tid == 0) sh_ta = 0;
    __syncthreads();
    if (poss >= 0) atomicMax(&sh_ta, poss + 1);
    __syncthreads();
    if (tid == 0) g_tactive = sh_ta;
}

// ---------------------------------------------------------------------------
// K2: two-phase kill search + fused reduction.
// Phase A: stream u2 chunk, filter against thr, append candidates to a smem
//          list (NO data-dependent global loads in the loop).
// Phase B: burst-evaluate candidates: all u1 loads issue together (one
//          latency round), exact condition L2 > rm*L1 with 2 MUFU logs.
//   sigmoid(logit+noise) > 0.5  <=>  L2/L1 + eps < exp(logit) = r
//                               <=>  L2 > (r - eps)*L1     (L1 < 0 flips)
// ---------------------------------------------------------------------------
__global__ void __launch_bounds__(256) kill_kernel(const float* __restrict__ u1,
                                                   const float* __restrict__ u2,
                                                   float* __restrict__ out) {
    __shared__ float4   s_u2[CH][256];   // 32 KB staging
    __shared__ float    s_val[LCAP];     // 8 KB candidate u2 values
    __shared__ uint32_t s_pk[LCAP];      // 8 KB candidate packed indices
    __shared__ float2   s_row[CH];
    __shared__ int      s_cnt;
    __shared__ bool     is_last;

    const int ta      = g_tactive;
    const int nchunks = (ta + CH - 1) / CH;
    const int tid     = threadIdx.x;
    const int q       = blockIdx.x * 256 + tid;          // quad index
    const float4* __restrict__ u2v = (const float4*)u2;
    const uint32_t s_base = (uint32_t)__cvta_generic_to_shared(&s_u2[0][tid]);

    for (int cy = blockIdx.y; cy < nchunks; cy += KGY) {
        const int t0 = cy * CH;
        if (tid == 0) s_cnt = 0;
        if (tid < CH) s_row[tid] = g_row[min(t0 + tid, TT - 1)];

        // stage CH u2 rows (fire-and-forget, all in flight)
#pragma unroll
        for (int i = 0; i < CH; ++i)
            cp_async16(s_base + i * (256 * 16), u2v + min(t0 + i, TT - 1) * (BB / 4) + q);
        cp_async_wait_all();
        __syncthreads();

        const int rmax = min(CH, ta - t0);
        // -------- Phase A: filter only, append candidates --------
#pragma unroll
        for (int i = 0; i < CH; ++i) {
            if (i >= rmax) break;
            const float  thr = s_row[i].x;
            const float4 vv  = s_u2[i][tid];
            const float  m   = fmaxf(fmaxf(vv.x, vv.y), fmaxf(vv.z, vv.w));
            if (m > thr) {
                const uint32_t pkb = ((uint32_t)i << 10) | ((uint32_t)tid << 2);
                float vs[4] = {vv.x, vv.y, vv.z, vv.w};
#pragma unroll
                for (int sub = 0; sub < 4; ++sub) {
                    if (vs[sub] > thr) {
                        int slot = atomicAdd(&s_cnt, 1);
                        if (slot < LCAP) {
                            s_val[slot] = vs[sub];
                            s_pk[slot]  = pkb | (uint32_t)sub;
                        } else {   // overflow fallback (statistically never)
                            int gl = blockIdx.x * 1024 + (int)(pkb & 1023u) + sub;
                            float L1 = __logf(u1[(t0 + i) * BB + gl] + EPSF);
                            float L2 = __logf(vs[sub] + EPSF);
                            if (L2 > s_row[i].y * L1) atomicMin(&g_tkill[gl], t0 + i);
                        }
                    }
                }
            }
        }
        __syncthreads();

        // -------- Phase B: burst evaluation --------
        const int n = min(s_cnt, LCAP);
        for (int j = tid; j < n; j += 256) {
            const uint32_t pk = s_pk[j];
            const float    v  = s_val[j];
            const int i  = (int)(pk >> 10);
            const int gl = blockIdx.x * 1024 + (int)(pk & 1023u);
            const int t  = t0 + i;
            float L1 = __logf(u1[t * BB + gl] + EPSF);
            float L2 = __logf(v + EPSF);
            if (L2 > s_row[i].y * L1) atomicMin(&g_tkill[gl], t);
        }
        __syncthreads();
    }

    // ---- fused reduction: last block gathers Pref[t_kill] and means ----
    __threadfence();
    if (tid == 0) is_last = (atomicAdd(&g_done, 1u) == NBLK - 1u);
    __syncthreads();
    if (!is_last) return;
    __threadfence();

    __shared__ double sh[256];
    int   kk[BB / 256];
#pragma unroll
    for (int it = 0; it < BB / 256; ++it) kk[it] = g_tkill[tid + it * 256];  // batch round 1
    double s = 0.0;
#pragma unroll
    for (int it = 0; it < BB / 256; ++it) s += (double)g_pref[kk[it]];        // batch round 2
    sh[tid] = s;
    __syncthreads();
#pragma unroll
    for (int off = 128; off > 0; off >>= 1) {
        if (tid < off) sh[tid] += sh[tid + off];
        __syncthreads();
    }
    if (tid == 0) out[0] = (float)(sh[0] / (double)BB);
}

// ---------------------------------------------------------------------------
extern "C" void kernel_launch(void* const* d_in, const int* in_sizes, int n_in,
                              void* d_out, int out_size) {
    const float* acts = (const float*)d_in[0];
    const float* u1   = (const float*)d_in[1];
    const float* u2   = (const float*)d_in[2];

    scan_kernel<<<1, NTH>>>(acts);

    dim3 grid(KGX, KGY);
    kill_kernel<<<grid, 256>>>(u1, u2, (float*)d_out);
}